// round 10
// baseline (speedup 1.0000x reference)
#include <cuda_runtime.h>

#define BB 4
#define TT 16
#define HH 64
#define WW 64
#define CC 32
#define FF 64
#define OC 256   // 4*F
#define PS 613   // smem plane stride (odd mod 32 -> conflict-free chunk loads)
#define HALO 612 // 18*34 halo plane elements

// ---------------- scratch (device globals; no allocations allowed) ----------
__device__ float g_xn[(size_t)BB*TT*HH*WW*CC];
__device__ float g_zx[(size_t)BB*TT*HH*WW*OC];
__device__ float g_ha[(size_t)BB*HH*WW*FF];   // h ping
__device__ float g_hb[(size_t)BB*HH*WW*FF];   // h pong
__device__ float g_c [(size_t)BB*HH*WW*FF];

// ---------------- LayerNorm over channel axis (C=32 = one warp) -------------
__global__ void ln_kernel(const float* __restrict__ x,
                          const float* __restrict__ gamma,
                          const float* __restrict__ beta) {
    int row  = blockIdx.x * 8 + (threadIdx.x >> 5);
    int lane = threadIdx.x & 31;
    float v = x[(size_t)row * CC + lane];
    float s = v, s2 = v * v;
    #pragma unroll
    for (int o = 16; o; o >>= 1) {
        s  += __shfl_xor_sync(0xffffffffu, s,  o);
        s2 += __shfl_xor_sync(0xffffffffu, s2, o);
    }
    float mu  = s * (1.f / 32.f);
    float var = s2 * (1.f / 32.f) - mu * mu;
    float inv = rsqrtf(var + 1e-3f);
    g_xn[(size_t)row * CC + lane] = (v - mu) * inv * gamma[lane] + beta[lane];
}

// ---------------- zero h(ping), c --------------------------------------------
__global__ void zero_hc_kernel() {
    int i = blockIdx.x * blockDim.x + threadIdx.x;
    if (i < BB * HH * WW * FF) { g_ha[i] = 0.f; g_c[i] = 0.f; }
}

// ---------------- input conv: zx = conv3x3(xn, Wx) + b ----------------------
// grid: (ocb=8, tile=8, bt=64), block 256, tile 32x16, 2 px/thread (R7-proven).
__global__ __launch_bounds__(256, 2) void convx_kernel(const float* __restrict__ Wx,
                                                       const float* __restrict__ bias) {
    extern __shared__ float sm[];
    float* s_in = sm;                 // 32 * 613
    float* s_w  = sm + 32 * PS;       // 9216

    int ocb  = blockIdx.x;
    int tile = blockIdx.y;
    int bt   = blockIdx.z;
    int tid  = threadIdx.x;
    int ty0 = (tile >> 1) * 16, tx0 = (tile & 1) * 32;
    int oc0 = ocb * 32;
    int px = tid & 31, py = tid >> 5;
    int y1 = ty0 + py, y2 = y1 + 8, x = tx0 + px;

    const float* xin = g_xn + (size_t)bt * HH * WW * CC;

    for (int i = tid; i < 8 * HALO; i += 256) {
        int c4 = (i & 7) * 4, sp = i >> 3;
        int ry = sp / 34, rx = sp - ry * 34;
        int gy = ty0 - 1 + ry, gx = tx0 - 1 + rx;
        float4 v = make_float4(0.f, 0.f, 0.f, 0.f);
        if (gy >= 0 && gy < HH && gx >= 0 && gx < WW)
            v = *(const float4*)(xin + ((size_t)gy * WW + gx) * CC + c4);
        s_in[(c4+0)*PS + sp] = v.x; s_in[(c4+1)*PS + sp] = v.y;
        s_in[(c4+2)*PS + sp] = v.z; s_in[(c4+3)*PS + sp] = v.w;
    }
    for (int i = tid; i < 9 * CC * 32; i += 256) {
        int oc = i & 31, rest = i >> 5;          // rest = kp*32 + ic
        s_w[i] = Wx[(size_t)rest * OC + oc0 + oc];
    }
    __syncthreads();

    float acc1[32], acc2[32];
    #pragma unroll
    for (int oc = 0; oc < 32; oc++) { float bv = bias[oc0 + oc]; acc1[oc] = bv; acc2[oc] = bv; }

    #pragma unroll
    for (int kp = 0; kp < 9; kp++) {
        int ky = kp / 3, kx = kp - 3 * ky;
        int spb = (py + ky) * 34 + px + kx;
        const float* wk = s_w + kp * 1024;
        #pragma unroll 4
        for (int ic = 0; ic < CC; ic++) {
            float a1 = s_in[ic * PS + spb];
            float a2 = s_in[ic * PS + spb + 272];     // +8 rows
            const float4* w4 = (const float4*)(wk + ic * 32);
            #pragma unroll
            for (int j = 0; j < 8; j++) {
                float4 w = w4[j];
                acc1[4*j+0] += a1 * w.x; acc1[4*j+1] += a1 * w.y;
                acc1[4*j+2] += a1 * w.z; acc1[4*j+3] += a1 * w.w;
                acc2[4*j+0] += a2 * w.x; acc2[4*j+1] += a2 * w.y;
                acc2[4*j+2] += a2 * w.z; acc2[4*j+3] += a2 * w.w;
            }
        }
    }
    float* o1 = g_zx + (((size_t)bt * HH + y1) * WW + x) * OC + oc0;
    float* o2 = g_zx + (((size_t)bt * HH + y2) * WW + x) * OC + oc0;
    #pragma unroll
    for (int j = 0; j < 8; j++) {
        ((float4*)o1)[j] = make_float4(acc1[4*j], acc1[4*j+1], acc1[4*j+2], acc1[4*j+3]);
        ((float4*)o2)[j] = make_float4(acc2[4*j], acc2[4*j+1], acc2[4*j+2], acc2[4*j+3]);
    }
}

// ---------------- recurrent conv + fused gates + fused 2x2 maxpool ----------
// grid: (fb=8, tile=8, b=4).  Block covers f-channels [fb*8, fb*8+8) across
// all 4 gates.  Thread owns pixel pair (2py, 2py+1) -> vertical pool pair;
// horizontal pool partner via shfl.xor(1).  Scalar FFMA inner loop (R7-proven).
__global__ __launch_bounds__(256, 2) void convh_kernel(const float* __restrict__ Wh,
                                                       const float* __restrict__ hin,
                                                       float* __restrict__ hout,
                                                       float* __restrict__ out, int t) {
    extern __shared__ float sm[];
    float* s_in = sm;                 // 32 * 613 (one 32-channel chunk)
    float* s_w  = sm + 32 * PS;       // 9216

    int fb   = blockIdx.x;
    int tile = blockIdx.y;
    int b    = blockIdx.z;
    int tid  = threadIdx.x;
    int ty0 = (tile >> 1) * 16, tx0 = (tile & 1) * 32;
    int f0 = fb * 8;
    int px = tid & 31, py = tid >> 5;          // py 0..7
    int y1 = ty0 + 2 * py, y2 = y1 + 1, x = tx0 + px;

    // acc layout: [gate*8 + j], j = local f-channel
    float acc1[32], acc2[32];
    {
        const float* zb1 = g_zx + (((((size_t)b * TT) + t) * HH + y1) * WW + x) * OC;
        const float* zb2 = g_zx + (((((size_t)b * TT) + t) * HH + y2) * WW + x) * OC;
        #pragma unroll
        for (int g = 0; g < 4; g++) {
            const float4* zp1 = (const float4*)(zb1 + g * 64 + f0);
            const float4* zp2 = (const float4*)(zb2 + g * 64 + f0);
            float4 v0 = zp1[0], v1 = zp1[1];
            acc1[g*8+0] = v0.x; acc1[g*8+1] = v0.y; acc1[g*8+2] = v0.z; acc1[g*8+3] = v0.w;
            acc1[g*8+4] = v1.x; acc1[g*8+5] = v1.y; acc1[g*8+6] = v1.z; acc1[g*8+7] = v1.w;
            float4 w0 = zp2[0], w1 = zp2[1];
            acc2[g*8+0] = w0.x; acc2[g*8+1] = w0.y; acc2[g*8+2] = w0.z; acc2[g*8+3] = w0.w;
            acc2[g*8+4] = w1.x; acc2[g*8+5] = w1.y; acc2[g*8+6] = w1.z; acc2[g*8+7] = w1.w;
        }
    }

    const float* hb = hin + (size_t)b * HH * WW * FF;

    for (int ch0 = 0; ch0 < FF; ch0 += 32) {
        if (ch0) __syncthreads();
        for (int i = tid; i < 8 * HALO; i += 256) {
            int c4 = (i & 7) * 4, sp = i >> 3;
            int ry = sp / 34, rx = sp - ry * 34;
            int gy = ty0 - 1 + ry, gx = tx0 - 1 + rx;
            float4 v = make_float4(0.f, 0.f, 0.f, 0.f);
            if (gy >= 0 && gy < HH && gx >= 0 && gx < WW)
                v = *(const float4*)(hb + ((size_t)gy * WW + gx) * FF + ch0 + c4);
            s_in[(c4+0)*PS + sp] = v.x; s_in[(c4+1)*PS + sp] = v.y;
            s_in[(c4+2)*PS + sp] = v.z; s_in[(c4+3)*PS + sp] = v.w;
        }
        // weight chunk [kp][icl][gate*8+j]
        for (int i = tid; i < 9216; i += 256) {
            int ocl = i & 31, rest = i >> 5, kp = rest >> 5, icl = rest & 31;
            int gate = ocl >> 3, j = ocl & 7;
            s_w[i] = Wh[((size_t)kp * FF + ch0 + icl) * OC + gate * 64 + f0 + j];
        }
        __syncthreads();

        #pragma unroll
        for (int kp = 0; kp < 9; kp++) {
            int ky = kp / 3, kx = kp - 3 * ky;
            int spb = (2 * py + ky) * 34 + px + kx;   // row y1-1+ky of halo
            const float* wk = s_w + kp * 1024;
            #pragma unroll 4
            for (int icl = 0; icl < 32; icl++) {
                float a1 = s_in[icl * PS + spb];
                float a2 = s_in[icl * PS + spb + 34];  // next row (y2)
                const float4* w4 = (const float4*)(wk + icl * 32);
                #pragma unroll
                for (int j = 0; j < 8; j++) {
                    float4 w = w4[j];
                    acc1[4*j+0] += a1 * w.x; acc1[4*j+1] += a1 * w.y;
                    acc1[4*j+2] += a1 * w.z; acc1[4*j+3] += a1 * w.w;
                    acc2[4*j+0] += a2 * w.x; acc2[4*j+1] += a2 * w.y;
                    acc2[4*j+2] += a2 * w.z; acc2[4*j+3] += a2 * w.w;
                }
            }
        }
    }

    // ---- fused gate epilogue (both rows) + 2x2 maxpool via shfl ----
    float pm[8];
    #pragma unroll
    for (int pp = 0; pp < 2; pp++) {
        float* A = pp ? acc2 : acc1;
        int y = pp ? y2 : y1;
        size_t pix = ((size_t)b * HH + y) * WW + x;
        float* cp = g_c  + pix * FF + f0;
        float* hp = hout + pix * FF + f0;
        #pragma unroll
        for (int j = 0; j < 8; j++) {
            float ig = __saturatef(0.2f * A[0*8+j] + 0.5f);
            float fg = __saturatef(0.2f * A[1*8+j] + 0.5f);
            float og = __saturatef(0.2f * A[3*8+j] + 0.5f);
            float c  = fg * cp[j] + ig * tanhf(A[2*8+j]);
            cp[j] = c;
            float h = og * tanhf(c);
            hp[j] = h;
            pm[j] = pp ? fmaxf(pm[j], h) : h;
        }
    }
    #pragma unroll
    for (int j = 0; j < 8; j++) {
        float o = __shfl_xor_sync(0xffffffffu, pm[j], 1);
        pm[j] = fmaxf(pm[j], o);
    }
    if (!(px & 1)) {
        float* op = out + ((((size_t)b * TT + t) * 32 + (ty0 >> 1) + py) * 32
                           + ((tx0 + px) >> 1)) * FF + f0;
        #pragma unroll
        for (int j = 0; j < 8; j += 4)
            *(float4*)(op + j) = make_float4(pm[j], pm[j+1], pm[j+2], pm[j+3]);
    }
}

// ---------------- launch ----------------------------------------------------
extern "C" void kernel_launch(void* const* d_in, const int* in_sizes, int n_in,
                              void* d_out, int out_size) {
    const float* x     = (const float*)d_in[0];
    const float* gamma = (const float*)d_in[1];
    const float* beta  = (const float*)d_in[2];
    const float* Wx    = (const float*)d_in[3];
    const float* Wh    = (const float*)d_in[4];
    const float* bias  = (const float*)d_in[5];
    float* out = (float*)d_out;

    const int SMEM = (32 * PS + 9 * 32 * 32) * 4;   // 115328 B
    cudaFuncSetAttribute(convx_kernel, cudaFuncAttributeMaxDynamicSharedMemorySize, SMEM);
    cudaFuncSetAttribute(convh_kernel, cudaFuncAttributeMaxDynamicSharedMemorySize, SMEM);

    float *d_ha, *d_hb;
    cudaGetSymbolAddress((void**)&d_ha, g_ha);
    cudaGetSymbolAddress((void**)&d_hb, g_hb);

    // LayerNorm
    ln_kernel<<<(BB * TT * HH * WW) / 8, 256>>>(x, gamma, beta);

    // zero h(ping), c (every call: deterministic)
    zero_hc_kernel<<<(BB * HH * WW * FF + 255) / 256, 256>>>();

    // input conv over all timesteps at once
    convx_kernel<<<dim3(8, 8, BB * TT), 256, SMEM>>>(Wx, bias);

    // recurrent loop: h ping-pongs between g_ha and g_hb; gates+pool fused
    for (int t = 0; t < TT; t++) {
        const float* hin = (t & 1) ? d_hb : d_ha;
        float*       hout = (t & 1) ? d_ha : d_hb;
        convh_kernel<<<dim3(8, 8, BB), 256, SMEM>>>(Wh, hin, hout, out, t);
    }
}

// round 11
// speedup vs baseline: 1.1891x; 1.1891x over previous
#include <cuda_runtime.h>

#define BB 4
#define TT 16
#define HH 64
#define WW 64
#define CC 32
#define FF 64
#define OC 256   // 4*F
#define PS 613   // smem plane stride (odd mod 32 -> conflict-free chunk loads)
#define HALO 612 // 18*34 halo plane elements

// ---------------- scratch (device globals; no allocations allowed) ----------
__device__ float g_xn[(size_t)BB*TT*HH*WW*CC];
__device__ float g_zx[(size_t)BB*TT*HH*WW*OC];
__device__ float g_h [(size_t)BB*HH*WW*FF];
__device__ float g_c [(size_t)BB*HH*WW*FF];
__device__ float g_z0[(size_t)BB*HH*WW*OC];   // partial: ic chunk 0 (+ zx)
__device__ float g_z1[(size_t)BB*HH*WW*OC];   // partial: ic chunk 1

// ---------------- LayerNorm over channel axis (C=32 = one warp) -------------
__global__ void ln_kernel(const float* __restrict__ x,
                          const float* __restrict__ gamma,
                          const float* __restrict__ beta) {
    int row  = blockIdx.x * 8 + (threadIdx.x >> 5);
    int lane = threadIdx.x & 31;
    float v = x[(size_t)row * CC + lane];
    float s = v, s2 = v * v;
    #pragma unroll
    for (int o = 16; o; o >>= 1) {
        s  += __shfl_xor_sync(0xffffffffu, s,  o);
        s2 += __shfl_xor_sync(0xffffffffu, s2, o);
    }
    float mu  = s * (1.f / 32.f);
    float var = s2 * (1.f / 32.f) - mu * mu;
    float inv = rsqrtf(var + 1e-3f);
    g_xn[(size_t)row * CC + lane] = (v - mu) * inv * gamma[lane] + beta[lane];
}

// ---------------- zero h, c --------------------------------------------------
__global__ void zero_hc_kernel() {
    int i = blockIdx.x * blockDim.x + threadIdx.x;
    if (i < BB * HH * WW * FF) { g_h[i] = 0.f; g_c[i] = 0.f; }
}

// ---------------- input conv: zx = conv3x3(xn, Wx) + b ----------------------
// grid: (ocb=8, tile=8, bt=64), block 256, tile 32x16, 2 px/thread (R7-proven).
__global__ __launch_bounds__(256, 2) void convx_kernel(const float* __restrict__ Wx,
                                                       const float* __restrict__ bias) {
    extern __shared__ float sm[];
    float* s_in = sm;                 // 32 * 613
    float* s_w  = sm + 32 * PS;       // 9216

    int ocb  = blockIdx.x;
    int tile = blockIdx.y;
    int bt   = blockIdx.z;
    int tid  = threadIdx.x;
    int ty0 = (tile >> 1) * 16, tx0 = (tile & 1) * 32;
    int oc0 = ocb * 32;
    int px = tid & 31, py = tid >> 5;
    int y1 = ty0 + py, y2 = y1 + 8, x = tx0 + px;

    const float* xin = g_xn + (size_t)bt * HH * WW * CC;

    for (int i = tid; i < 8 * HALO; i += 256) {
        int c4 = (i & 7) * 4, sp = i >> 3;
        int ry = sp / 34, rx = sp - ry * 34;
        int gy = ty0 - 1 + ry, gx = tx0 - 1 + rx;
        float4 v = make_float4(0.f, 0.f, 0.f, 0.f);
        if (gy >= 0 && gy < HH && gx >= 0 && gx < WW)
            v = *(const float4*)(xin + ((size_t)gy * WW + gx) * CC + c4);
        s_in[(c4+0)*PS + sp] = v.x; s_in[(c4+1)*PS + sp] = v.y;
        s_in[(c4+2)*PS + sp] = v.z; s_in[(c4+3)*PS + sp] = v.w;
    }
    for (int i = tid; i < 9 * CC * 32; i += 256) {
        int oc = i & 31, rest = i >> 5;          // rest = kp*32 + ic
        s_w[i] = Wx[(size_t)rest * OC + oc0 + oc];
    }
    __syncthreads();

    float acc1[32], acc2[32];
    #pragma unroll
    for (int oc = 0; oc < 32; oc++) { float bv = bias[oc0 + oc]; acc1[oc] = bv; acc2[oc] = bv; }

    #pragma unroll
    for (int kp = 0; kp < 9; kp++) {
        int ky = kp / 3, kx = kp - 3 * ky;
        int spb = (py + ky) * 34 + px + kx;
        const float* wk = s_w + kp * 1024;
        #pragma unroll 4
        for (int ic = 0; ic < CC; ic++) {
            float a1 = s_in[ic * PS + spb];
            float a2 = s_in[ic * PS + spb + 272];     // +8 rows
            const float4* w4 = (const float4*)(wk + ic * 32);
            #pragma unroll
            for (int j = 0; j < 8; j++) {
                float4 w = w4[j];
                acc1[4*j+0] += a1 * w.x; acc1[4*j+1] += a1 * w.y;
                acc1[4*j+2] += a1 * w.z; acc1[4*j+3] += a1 * w.w;
                acc2[4*j+0] += a2 * w.x; acc2[4*j+1] += a2 * w.y;
                acc2[4*j+2] += a2 * w.z; acc2[4*j+3] += a2 * w.w;
            }
        }
    }
    float* o1 = g_zx + (((size_t)bt * HH + y1) * WW + x) * OC + oc0;
    float* o2 = g_zx + (((size_t)bt * HH + y2) * WW + x) * OC + oc0;
    #pragma unroll
    for (int j = 0; j < 8; j++) {
        ((float4*)o1)[j] = make_float4(acc1[4*j], acc1[4*j+1], acc1[4*j+2], acc1[4*j+3]);
        ((float4*)o2)[j] = make_float4(acc2[4*j], acc2[4*j+1], acc2[4*j+2], acc2[4*j+3]);
    }
}

// ---------------- recurrent conv partial: one 32-ic chunk -------------------
// grid: (ocb=8, tile=8, bc=8) where bc = b*2 + chunk.  512 blocks -> balanced.
// chunk 0 seeds acc from g_zx[t] and writes g_z0; chunk 1 seeds 0, writes g_z1.
__global__ __launch_bounds__(256, 2) void convh_kernel(const float* __restrict__ Wh, int t) {
    extern __shared__ float sm[];
    float* s_in = sm;                 // 32 * 613
    float* s_w  = sm + 32 * PS;       // 9216

    int ocb  = blockIdx.x;
    int tile = blockIdx.y;
    int b    = blockIdx.z >> 1;
    int chunk= blockIdx.z & 1;
    int ch0  = chunk * 32;
    int tid  = threadIdx.x;
    int ty0 = (tile >> 1) * 16, tx0 = (tile & 1) * 32;
    int oc0 = ocb * 32;
    int px = tid & 31, py = tid >> 5;
    int y1 = ty0 + py, y2 = y1 + 8, x = tx0 + px;

    const float* hb = g_h + (size_t)b * HH * WW * FF;

    for (int i = tid; i < 8 * HALO; i += 256) {
        int c4 = (i & 7) * 4, sp = i >> 3;
        int ry = sp / 34, rx = sp - ry * 34;
        int gy = ty0 - 1 + ry, gx = tx0 - 1 + rx;
        float4 v = make_float4(0.f, 0.f, 0.f, 0.f);
        if (gy >= 0 && gy < HH && gx >= 0 && gx < WW)
            v = *(const float4*)(hb + ((size_t)gy * WW + gx) * FF + ch0 + c4);
        s_in[(c4+0)*PS + sp] = v.x; s_in[(c4+1)*PS + sp] = v.y;
        s_in[(c4+2)*PS + sp] = v.z; s_in[(c4+3)*PS + sp] = v.w;
    }
    for (int i = tid; i < 9216; i += 256) {
        int oc = i & 31, rest = i >> 5, kp = rest >> 5, icl = rest & 31;
        s_w[i] = Wh[((size_t)kp * FF + ch0 + icl) * OC + oc0 + oc];
    }
    __syncthreads();

    float acc1[32], acc2[32];
    if (chunk == 0) {
        const float4* z1 = (const float4*)(g_zx + (((((size_t)b * TT) + t) * HH + y1) * WW + x) * OC + oc0);
        const float4* z2 = (const float4*)(g_zx + (((((size_t)b * TT) + t) * HH + y2) * WW + x) * OC + oc0);
        #pragma unroll
        for (int j = 0; j < 8; j++) {
            float4 v = z1[j];
            acc1[4*j+0] = v.x; acc1[4*j+1] = v.y; acc1[4*j+2] = v.z; acc1[4*j+3] = v.w;
            float4 w = z2[j];
            acc2[4*j+0] = w.x; acc2[4*j+1] = w.y; acc2[4*j+2] = w.z; acc2[4*j+3] = w.w;
        }
    } else {
        #pragma unroll
        for (int oc = 0; oc < 32; oc++) { acc1[oc] = 0.f; acc2[oc] = 0.f; }
    }

    #pragma unroll
    for (int kp = 0; kp < 9; kp++) {
        int ky = kp / 3, kx = kp - 3 * ky;
        int spb = (py + ky) * 34 + px + kx;
        const float* wk = s_w + kp * 1024;
        #pragma unroll 4
        for (int icl = 0; icl < 32; icl++) {
            float a1 = s_in[icl * PS + spb];
            float a2 = s_in[icl * PS + spb + 272];
            const float4* w4 = (const float4*)(wk + icl * 32);
            #pragma unroll
            for (int j = 0; j < 8; j++) {
                float4 w = w4[j];
                acc1[4*j+0] += a1 * w.x; acc1[4*j+1] += a1 * w.y;
                acc1[4*j+2] += a1 * w.z; acc1[4*j+3] += a1 * w.w;
                acc2[4*j+0] += a2 * w.x; acc2[4*j+1] += a2 * w.y;
                acc2[4*j+2] += a2 * w.z; acc2[4*j+3] += a2 * w.w;
            }
        }
    }

    float* zp = chunk ? g_z1 : g_z0;
    float* o1 = zp + (((size_t)b * HH + y1) * WW + x) * OC + oc0;
    float* o2 = zp + (((size_t)b * HH + y2) * WW + x) * OC + oc0;
    #pragma unroll
    for (int j = 0; j < 8; j++) {
        ((float4*)o1)[j] = make_float4(acc1[4*j], acc1[4*j+1], acc1[4*j+2], acc1[4*j+3]);
        ((float4*)o2)[j] = make_float4(acc2[4*j], acc2[4*j+1], acc2[4*j+2], acc2[4*j+3]);
    }
}

// ---------------- LSTM gates + MaxPool(2x2) fused (R7-proven) ---------------
// One thread handles a 2x2 pixel quad for one feature f; z = z0 + z1.
__global__ void gatepool_kernel(float* __restrict__ out, int t) {
    int i = blockIdx.x * blockDim.x + threadIdx.x;   // B*32*32*F = 262144
    if (i >= BB * 32 * 32 * FF) return;
    int f = i & 63;
    int r = i >> 6;
    int xo = r & 31; r >>= 5;
    int yo = r & 31;
    int b  = r >> 5;

    float m = -1e30f;
    #pragma unroll
    for (int dy = 0; dy < 2; dy++) {
        #pragma unroll
        for (int dx = 0; dx < 2; dx++) {
            size_t pix = ((size_t)b * HH + (yo * 2 + dy)) * WW + (xo * 2 + dx);
            const float* z0 = g_z0 + pix * OC;
            const float* z1 = g_z1 + pix * OC;
            float zi = z0[f]       + z1[f];
            float zf = z0[64 + f]  + z1[64 + f];
            float zc = z0[128 + f] + z1[128 + f];
            float zo_= z0[192 + f] + z1[192 + f];
            float ig = __saturatef(0.2f * zi + 0.5f);
            float fg = __saturatef(0.2f * zf + 0.5f);
            float og = __saturatef(0.2f * zo_ + 0.5f);
            size_t hi = pix * FF + f;
            float c  = fg * g_c[hi] + ig * tanhf(zc);
            g_c[hi] = c;
            float h = og * tanhf(c);
            g_h[hi] = h;
            m = fmaxf(m, h);
        }
    }
    out[(((((size_t)b * TT) + t) * 32 + yo) * 32 + xo) * FF + f] = m;
}

// ---------------- launch ----------------------------------------------------
extern "C" void kernel_launch(void* const* d_in, const int* in_sizes, int n_in,
                              void* d_out, int out_size) {
    const float* x     = (const float*)d_in[0];
    const float* gamma = (const float*)d_in[1];
    const float* beta  = (const float*)d_in[2];
    const float* Wx    = (const float*)d_in[3];
    const float* Wh    = (const float*)d_in[4];
    const float* bias  = (const float*)d_in[5];
    float* out = (float*)d_out;

    const int SMEM = (32 * PS + 9 * 32 * 32) * 4;   // 115328 B
    cudaFuncSetAttribute(convx_kernel, cudaFuncAttributeMaxDynamicSharedMemorySize, SMEM);
    cudaFuncSetAttribute(convh_kernel, cudaFuncAttributeMaxDynamicSharedMemorySize, SMEM);

    // LayerNorm
    ln_kernel<<<(BB * TT * HH * WW) / 8, 256>>>(x, gamma, beta);

    // zero h, c (every call: deterministic)
    zero_hc_kernel<<<(BB * HH * WW * FF + 255) / 256, 256>>>();

    // input conv over all timesteps at once
    convx_kernel<<<dim3(8, 8, BB * TT), 256, SMEM>>>(Wx, bias);

    // recurrent loop: 512-block balanced convh (ic chunks split across blocks)
    for (int t = 0; t < TT; t++) {
        convh_kernel<<<dim3(8, 8, BB * 2), 256, SMEM>>>(Wh, t);
        gatepool_kernel<<<(BB * 32 * 32 * FF + 255) / 256, 256>>>(out, t);
    }
}

// round 12
// speedup vs baseline: 2.8023x; 2.3567x over previous
#include <cuda_runtime.h>
#include <cuda_bf16.h>

#define BB 4
#define TT 16
#define HH 64
#define WW 64
#define CC 32
#define FF 64
#define OC 256   // 4*F

typedef unsigned int u32;

// ---------------- scratch (device globals; no allocations allowed) ----------
__device__ __nv_bfloat16 g_xh[(size_t)BB*TT*HH*WW*CC];   // LN output hi
__device__ __nv_bfloat16 g_xl[(size_t)BB*TT*HH*WW*CC];   // LN output lo
__device__ float         g_zx[(size_t)BB*TT*HH*WW*OC];   // input-conv result
__device__ __nv_bfloat16 g_hh[(size_t)BB*HH*WW*FF];      // h hi
__device__ __nv_bfloat16 g_hl[(size_t)BB*HH*WW*FF];      // h lo
__device__ float         g_c [(size_t)BB*HH*WW*FF];
__device__ float         g_z [(size_t)BB*HH*WW*OC];      // recurrent conv result

// ---------------- bf16 mma (Ampere-layout m16n8k16, fp32 accum) -------------
#define MMA_BF16(d, a0,a1,a2,a3, b0,b1)                                        \
    asm volatile("mma.sync.aligned.m16n8k16.row.col.f32.bf16.bf16.f32 "        \
        "{%0,%1,%2,%3}, {%4,%5,%6,%7}, {%8,%9}, {%0,%1,%2,%3};"                \
        : "+f"((d)[0]), "+f"((d)[1]), "+f"((d)[2]), "+f"((d)[3])               \
        : "r"(a0), "r"(a1), "r"(a2), "r"(a3), "r"(b0), "r"(b1))

// ---------------- LayerNorm over channel axis -> bf16 hi/lo -----------------
__global__ void ln_kernel(const float* __restrict__ x,
                          const float* __restrict__ gamma,
                          const float* __restrict__ beta) {
    int row  = blockIdx.x * 8 + (threadIdx.x >> 5);
    int lane = threadIdx.x & 31;
    float v = x[(size_t)row * CC + lane];
    float s = v, s2 = v * v;
    #pragma unroll
    for (int o = 16; o; o >>= 1) {
        s  += __shfl_xor_sync(0xffffffffu, s,  o);
        s2 += __shfl_xor_sync(0xffffffffu, s2, o);
    }
    float mu  = s * (1.f / 32.f);
    float var = s2 * (1.f / 32.f) - mu * mu;
    float inv = rsqrtf(var + 1e-3f);
    float xn = (v - mu) * inv * gamma[lane] + beta[lane];
    __nv_bfloat16 hi = __float2bfloat16(xn);
    size_t idx = (size_t)row * CC + lane;
    g_xh[idx] = hi;
    g_xl[idx] = __float2bfloat16(xn - __bfloat162float(hi));
}

// ---------------- zero h(hi/lo), c -------------------------------------------
__global__ void zero_hc_kernel() {
    int i = blockIdx.x * blockDim.x + threadIdx.x;
    if (i < BB * HH * WW * FF) {
        g_c[i] = 0.f;
        __nv_bfloat16 z = __float2bfloat16(0.f);
        g_hh[i] = z; g_hl[i] = z;
    }
}

// ============================================================================
// Implicit-GEMM 3x3 conv via bf16 mma with hi/lo split.
//   block = 256 thr (8 warps), spatial tile 16x16, 32 out channels.
//   Warp w owns tile rows {w, w+8}; M16 = 16 x-positions of one row.
//   smem A: [324 halo sp][144B row: 32 bf16 hi | 32 bf16 lo | pad] (18x18 halo)
//   smem B: [9*32 oc-rows][144B: 32 ic hi | 32 ic lo | pad]
//   144B stride => fragment LDS covers all 32 banks (gid*36+tig mod 32).
//   IC processed in chunks of 32; 3 mma terms per tile: AhBh + AhBl + AlBh.
// ============================================================================
template<int IC, bool SEEDZ>
__global__ __launch_bounds__(256, 2) void conv_mma(
    const __nv_bfloat16* __restrict__ Ahi, const __nv_bfloat16* __restrict__ Alo,
    const float* __restrict__ W,      // [9][IC][OC] fp32
    const float* __restrict__ bias,   // convx only
    const float* __restrict__ zseed,  // convh only: g_zx
    float* __restrict__ zout, int t_step)
{
    extern __shared__ __align__(16) unsigned char smraw[];
    char* s_a = (char*)smraw;            // 324*144 = 46656 B
    char* s_b = (char*)smraw + 46656;    // 288*144 = 41472 B

    int ocb = blockIdx.x, tile = blockIdx.y, img = blockIdx.z;
    int tid = threadIdx.x;
    int ty0 = (tile >> 2) * 16, tx0 = (tile & 3) * 16;
    int oc0 = ocb * 32;
    int w = tid >> 5, lane = tid & 31, gid = lane >> 2, tig = lane & 3;

    // acc[t][n][0..3]: t = row (w / w+8), n = oc octet.  c0/c1: x=tx0+gid,
    // c2/c3: x=tx0+gid+8; oc = oc0 + n*8 + tig*2 (+1).
    float acc[2][4][4];
    if (SEEDZ) {
        const float* zs = zseed + ((size_t)(img * TT + t_step) * HH * WW) * OC;
        #pragma unroll
        for (int t = 0; t < 2; t++) {
            int y = ty0 + w + t * 8;
            const float* r1 = zs + ((size_t)y * WW + tx0 + gid) * OC + oc0 + tig * 2;
            #pragma unroll
            for (int n = 0; n < 4; n++) {
                float2 v1 = *(const float2*)(r1 + n * 8);
                float2 v2 = *(const float2*)(r1 + 8 * OC + n * 8);
                acc[t][n][0] = v1.x; acc[t][n][1] = v1.y;
                acc[t][n][2] = v2.x; acc[t][n][3] = v2.y;
            }
        }
    } else {
        #pragma unroll
        for (int n = 0; n < 4; n++) {
            float b0 = bias[oc0 + n * 8 + tig * 2];
            float b1 = bias[oc0 + n * 8 + tig * 2 + 1];
            #pragma unroll
            for (int t = 0; t < 2; t++) {
                acc[t][n][0] = b0; acc[t][n][1] = b1;
                acc[t][n][2] = b0; acc[t][n][3] = b1;
            }
        }
    }

    const __nv_bfloat16* Ah = Ahi + (size_t)img * HH * WW * IC;
    const __nv_bfloat16* Al = Alo + (size_t)img * HH * WW * IC;

    for (int ch0 = 0; ch0 < IC; ch0 += 32) {
        if (ch0) __syncthreads();
        // ---- stage A halo tile (18x18), bf16 hi|lo, zero-filled bounds ----
        for (int i = tid; i < 324 * 8; i += 256) {
            int sp = i >> 3, r = i & 7;                 // r<4: hi vec, else lo
            int ry = sp / 18, rx = sp - ry * 18;
            int gy = ty0 - 1 + ry, gx = tx0 - 1 + rx;
            uint4 v = make_uint4(0u, 0u, 0u, 0u);
            if (gy >= 0 && gy < HH && gx >= 0 && gx < WW) {
                const __nv_bfloat16* src = (r < 4 ? Ah : Al)
                    + ((size_t)gy * WW + gx) * IC + ch0 + ((r & 3) << 3);
                v = *(const uint4*)src;
            }
            *(uint4*)(s_a + sp * 144 + ((r & 3) << 4) + ((r < 4) ? 0 : 64)) = v;
        }
        // ---- stage B: W[kp][ic][oc] -> s_b[kp*32+oc][ic hi | ic lo] ----
        for (int i = tid; i < 9216; i += 256) {
            int oc = i & 31, rest = i >> 5, kp = rest >> 5, icl = rest & 31;
            float v = W[((size_t)kp * IC + ch0 + icl) * OC + oc0 + oc];
            __nv_bfloat16 h = __float2bfloat16(v);
            __nv_bfloat16 l = __float2bfloat16(v - __bfloat162float(h));
            __nv_bfloat16* br = (__nv_bfloat16*)(s_b + (kp * 32 + oc) * 144);
            br[icl] = h; br[32 + icl] = l;
        }
        __syncthreads();

        #pragma unroll 1
        for (int kp = 0; kp < 9; kp++) {
            int ky = (kp >= 6) ? 2 : ((kp >= 3) ? 1 : 0);
            int kx = kp - ky * 3;
            #pragma unroll
            for (int s = 0; s < 2; s++) {           // two k16 halves of chunk
                u32 bh[4][2], bl[4][2];
                #pragma unroll
                for (int n = 0; n < 4; n++) {
                    const char* bp = s_b + (kp * 32 + n * 8 + gid) * 144 + s * 32 + tig * 4;
                    bh[n][0] = *(const u32*)bp;        bh[n][1] = *(const u32*)(bp + 16);
                    bl[n][0] = *(const u32*)(bp + 64); bl[n][1] = *(const u32*)(bp + 80);
                }
                #pragma unroll
                for (int t = 0; t < 2; t++) {
                    const char* ap = s_a + ((w + 8 * t + ky) * 18 + gid + kx) * 144
                                   + s * 32 + tig * 4;
                    u32 ah0 = *(const u32*)ap;
                    u32 ah2 = *(const u32*)(ap + 16);
                    u32 ah1 = *(const u32*)(ap + 8 * 144);
                    u32 ah3 = *(const u32*)(ap + 8 * 144 + 16);
                    u32 al0 = *(const u32*)(ap + 64);
                    u32 al2 = *(const u32*)(ap + 80);
                    u32 al1 = *(const u32*)(ap + 8 * 144 + 64);
                    u32 al3 = *(const u32*)(ap + 8 * 144 + 80);
                    #pragma unroll
                    for (int n = 0; n < 4; n++) {
                        MMA_BF16(acc[t][n], ah0, ah1, ah2, ah3, bh[n][0], bh[n][1]);
                        MMA_BF16(acc[t][n], ah0, ah1, ah2, ah3, bl[n][0], bl[n][1]);
                        MMA_BF16(acc[t][n], al0, al1, al2, al3, bh[n][0], bh[n][1]);
                    }
                }
            }
        }
    }

    float* zo = zout + (size_t)img * HH * WW * OC;
    #pragma unroll
    for (int t = 0; t < 2; t++) {
        int y = ty0 + w + t * 8;
        float* r1 = zo + ((size_t)y * WW + tx0 + gid) * OC + oc0 + tig * 2;
        #pragma unroll
        for (int n = 0; n < 4; n++) {
            *(float2*)(r1 + n * 8)          = make_float2(acc[t][n][0], acc[t][n][1]);
            *(float2*)(r1 + 8 * OC + n * 8) = make_float2(acc[t][n][2], acc[t][n][3]);
        }
    }
}

// ---------------- LSTM gates + MaxPool(2x2) fused (R7-proven) ---------------
__global__ void gatepool_kernel(float* __restrict__ out, int t) {
    int i = blockIdx.x * blockDim.x + threadIdx.x;   // B*32*32*F = 262144
    if (i >= BB * 32 * 32 * FF) return;
    int f = i & 63;
    int r = i >> 6;
    int xo = r & 31; r >>= 5;
    int yo = r & 31;
    int b  = r >> 5;

    float m = -1e30f;
    #pragma unroll
    for (int dy = 0; dy < 2; dy++) {
        #pragma unroll
        for (int dx = 0; dx < 2; dx++) {
            size_t pix = ((size_t)b * HH + (yo * 2 + dy)) * WW + (xo * 2 + dx);
            const float* z = g_z + pix * OC;
            float zi = z[f], zf = z[64 + f], zc = z[128 + f], zo_ = z[192 + f];
            float ig = __saturatef(0.2f * zi + 0.5f);
            float fg = __saturatef(0.2f * zf + 0.5f);
            float og = __saturatef(0.2f * zo_ + 0.5f);
            size_t hi = pix * FF + f;
            float c  = fg * g_c[hi] + ig * tanhf(zc);
            g_c[hi] = c;
            float h = og * tanhf(c);
            __nv_bfloat16 hh = __float2bfloat16(h);
            g_hh[hi] = hh;
            g_hl[hi] = __float2bfloat16(h - __bfloat162float(hh));
            m = fmaxf(m, h);
        }
    }
    out[(((((size_t)b * TT) + t) * 32 + yo) * 32 + xo) * FF + f] = m;
}

// ---------------- launch ----------------------------------------------------
extern "C" void kernel_launch(void* const* d_in, const int* in_sizes, int n_in,
                              void* d_out, int out_size) {
    const float* x     = (const float*)d_in[0];
    const float* gamma = (const float*)d_in[1];
    const float* beta  = (const float*)d_in[2];
    const float* Wx    = (const float*)d_in[3];
    const float* Wh    = (const float*)d_in[4];
    const float* bias  = (const float*)d_in[5];
    float* out = (float*)d_out;

    const int SMEM = 46656 + 41472;   // 88128 B -> 2 CTAs/SM
    cudaFuncSetAttribute(conv_mma<CC, false>, cudaFuncAttributeMaxDynamicSharedMemorySize, SMEM);
    cudaFuncSetAttribute(conv_mma<FF, true >, cudaFuncAttributeMaxDynamicSharedMemorySize, SMEM);

    __nv_bfloat16 *d_xh, *d_xl, *d_hh, *d_hl;
    float *d_zx, *d_z;
    cudaGetSymbolAddress((void**)&d_xh, g_xh);
    cudaGetSymbolAddress((void**)&d_xl, g_xl);
    cudaGetSymbolAddress((void**)&d_hh, g_hh);
    cudaGetSymbolAddress((void**)&d_hl, g_hl);
    cudaGetSymbolAddress((void**)&d_zx, g_zx);
    cudaGetSymbolAddress((void**)&d_z,  g_z);

    // LayerNorm -> bf16 hi/lo
    ln_kernel<<<(BB * TT * HH * WW) / 8, 256>>>(x, gamma, beta);

    // zero h, c (every call: deterministic)
    zero_hc_kernel<<<(BB * HH * WW * FF + 255) / 256, 256>>>();

    // input conv over all timesteps at once (tensor pipe)
    conv_mma<CC, false><<<dim3(8, 16, BB * TT), 256, SMEM>>>(
        d_xh, d_xl, Wx, bias, nullptr, d_zx, 0);

    // recurrent loop
    for (int t = 0; t < TT; t++) {
        conv_mma<FF, true><<<dim3(8, 16, BB), 256, SMEM>>>(
            d_hh, d_hl, Wh, nullptr, d_zx, d_z, t);
        gatepool_kernel<<<(BB * 32 * 32 * FF + 255) / 256, 256>>>(out, t);
    }
}